// round 15
// baseline (speedup 1.0000x reference)
#include <cuda_runtime.h>
#include <cuda_fp16.h>
#include <cuda_bf16.h>
#include <math.h>
#include <stdint.h>

#define Nn 64
#define Tt 32
#define DA 1280
#define PP 16
#define HH 512
#define H4 2048
#define WD 300
#define KXP 320     // Wx K padded 300 -> 320
#define VV 32000

// ---------------- device scratch (no allocs allowed) ----------------
__device__ float g_cwT[DA * HH];            // conv_w transposed [c][h]
__device__ float g_Aproj[Nn * PP * HH];     // [n*16+p][512] fp32 (attention dots)
__device__ float g_h[2][Nn * HH];           // double-buffered h (fp32, producer dots)
__device__ float g_c[Nn * HH];
__device__ float g_w[Nn * PP];              // attention weights for current step
__device__ float g_xa[Tt * Nn * H4];        // x@Wx + b, row r = t*64+n
__device__ float g_AW[Nn * PP * H4];        // Aproj@Wattn, [n*16+p][2048]
__device__ unsigned int g_wflag[Tt];        // per-step producer flag

// fp16 operands for the vocab GEMM (K-major)
__device__ __align__(16) __half g_Ah[Nn * Tt * HH];       // [2048][512], row n*32+t
__device__ __align__(16) __half g_BhT[(size_t)VV * HH];   // [32000][512]

// bf16-split operands for xa / aw GEMMs (K-major)
__device__ __align__(16) __nv_bfloat16 g_Axh[Tt * Nn * KXP];   // gathered x, [2048][320]
__device__ __align__(16) __nv_bfloat16 g_Axl[Tt * Nn * KXP];
__device__ __align__(16) __nv_bfloat16 g_WxTh[H4 * KXP];       // Wx^T, [2048][320]
__device__ __align__(16) __nv_bfloat16 g_WxTl[H4 * KXP];
__device__ __align__(16) __nv_bfloat16 g_WaTh[H4 * HH];        // Wattn^T, [2048][512]
__device__ __align__(16) __nv_bfloat16 g_WaTl[H4 * HH];
__device__ __align__(16) __nv_bfloat16 g_APh[Nn * PP * HH];    // Aproj split, [1024][512]
__device__ __align__(16) __nv_bfloat16 g_APl[Nn * PP * HH];

// recurrent GEMM operands
__device__ __align__(16) __nv_bfloat16 g_WhPh[H4 * HH];  // permuted Wh^T hi, row pr=c*64+g*16+hcl
__device__ __align__(16) __nv_bfloat16 g_WhPl[H4 * HH];
__device__ __align__(16) __nv_bfloat16 g_Hh[Nn * HH];    // current h bf16 hi/lo, [64][512]
__device__ __align__(16) __nv_bfloat16 g_Hl[Nn * HH];

// ---------------- portable PTX helpers (sm_80+ features only) ----------------
__device__ __forceinline__ uint32_t smem_u32(const void* p) {
    uint32_t a;
    asm("{ .reg .u64 t; cvta.to.shared.u64 t, %1; cvt.u32.u64 %0, t; }" : "=r"(a) : "l"(p));
    return a;
}
__device__ __forceinline__ void cpasync16(uint32_t dst, const void* src) {
    asm volatile("cp.async.cg.shared.global [%0], [%1], 16;" :: "r"(dst), "l"(src) : "memory");
}
__device__ __forceinline__ void cp_commit() {
    asm volatile("cp.async.commit_group;" ::: "memory");
}
__device__ __forceinline__ void ldmx4(uint32_t* r, uint32_t addr) {
    asm volatile("ldmatrix.sync.aligned.m8n8.x4.shared.b16 {%0,%1,%2,%3}, [%4];"
                 : "=r"(r[0]), "=r"(r[1]), "=r"(r[2]), "=r"(r[3]) : "r"(addr));
}
__device__ __forceinline__ void mma16816h(float* d, const uint32_t* a, uint32_t b0, uint32_t b1) {
    asm volatile(
        "mma.sync.aligned.m16n8k16.row.col.f32.f16.f16.f32 "
        "{%0,%1,%2,%3}, {%4,%5,%6,%7}, {%8,%9}, {%0,%1,%2,%3};"
        : "+f"(d[0]), "+f"(d[1]), "+f"(d[2]), "+f"(d[3])
        : "r"(a[0]), "r"(a[1]), "r"(a[2]), "r"(a[3]), "r"(b0), "r"(b1));
}
__device__ __forceinline__ void mma16816b(float* d, const uint32_t* a, uint32_t b0, uint32_t b1) {
    asm volatile(
        "mma.sync.aligned.m16n8k16.row.col.f32.bf16.bf16.f32 "
        "{%0,%1,%2,%3}, {%4,%5,%6,%7}, {%8,%9}, {%0,%1,%2,%3};"
        : "+f"(d[0]), "+f"(d[1]), "+f"(d[2]), "+f"(d[3])
        : "r"(a[0]), "r"(a[1]), "r"(a[2]), "r"(a[3]), "r"(b0), "r"(b1));
}

// ---------------- K_init: zero producer flags (every launch -> replay-safe) ----------
__global__ void k_initflags() {
    if (threadIdx.x < Tt) g_wflag[threadIdx.x] = 0u;
}

// ---------------- K0: transpose conv_w [512][1280] -> g_cwT [1280][512] ----------------
__global__ void k_transpose(const float* __restrict__ w) {
    __shared__ float tile[32][33];
    int c0 = blockIdx.x * 32, h0 = blockIdx.y * 32;
    for (int i = threadIdx.y; i < 32; i += 8)
        tile[i][threadIdx.x] = w[(h0 + i) * DA + c0 + threadIdx.x];
    __syncthreads();
    for (int i = threadIdx.y; i < 32; i += 8)
        g_cwT[(c0 + i) * HH + h0 + threadIdx.x] = tile[threadIdx.x][i];
}

// ---------------- K1: Aproj (fp32 + bf16-split) + fused h0/c0 (+split) ----------------
__global__ void k_conv(const float* __restrict__ A, const float* __restrict__ cb) {
    int n = blockIdx.x >> 2, cg = blockIdx.x & 3;
    int j = cg * 128 + threadIdx.x;
    __shared__ float a_sm[256 * 16];
    float acc[16];
#pragma unroll
    for (int p = 0; p < 16; p++) acc[p] = 0.f;
    for (int k0 = 0; k0 < DA; k0 += 256) {
        __syncthreads();
        const float* src = A + ((size_t)n * DA + k0) * 16;
        for (int idx = threadIdx.x; idx < 256 * 16; idx += 128) a_sm[idx] = src[idx];
        __syncthreads();
#pragma unroll 4
        for (int kk = 0; kk < 256; kk++) {
            float w = g_cwT[(k0 + kk) * HH + j];
            const float4* ar = (const float4*)&a_sm[kk * 16];
            float4 a0 = ar[0], a1 = ar[1], a2 = ar[2], a3 = ar[3];
            acc[0]  += a0.x * w; acc[1]  += a0.y * w; acc[2]  += a0.z * w; acc[3]  += a0.w * w;
            acc[4]  += a1.x * w; acc[5]  += a1.y * w; acc[6]  += a1.z * w; acc[7]  += a1.w * w;
            acc[8]  += a2.x * w; acc[9]  += a2.y * w; acc[10] += a2.z * w; acc[11] += a2.w * w;
            acc[12] += a3.x * w; acc[13] += a3.y * w; acc[14] += a3.z * w; acc[15] += a3.w * w;
        }
    }
    float bb = cb[j];
    float s = 0.f;
#pragma unroll
    for (int p = 0; p < 16; p++) {
        float v = acc[p] + bb;
        size_t o = (size_t)(n * 16 + p) * HH + j;
        g_Aproj[o] = v;
        __nv_bfloat16 hi = __float2bfloat16(v);
        g_APh[o] = hi;
        g_APl[o] = __float2bfloat16(v - __bfloat162float(hi));
        s += acc[p];
    }
    s = s * (1.f / 16.f) + bb;          // mean_p(acc[p] + bb)
    g_h[0][n * HH + j] = s;
    g_c[n * HH + j] = s;
    __nv_bfloat16 hi = __float2bfloat16(s);
    g_Hh[n * HH + j] = hi;
    g_Hl[n * HH + j] = __float2bfloat16(s - __bfloat162float(hi));
}

// ---------------- K_convWx: Wx [300][2048] -> WxT hi/lo [2048][320] (zero-pad K) ------
__global__ void k_convWx(const float* __restrict__ Wx) {
    __shared__ float tile[32][33];
    int j0 = blockIdx.x * 32, k0 = blockIdx.y * 32;
    for (int i = threadIdx.y; i < 32; i += 8) {
        int k = k0 + i;
        tile[i][threadIdx.x] = (k < WD) ? Wx[(size_t)k * H4 + j0 + threadIdx.x] : 0.f;
    }
    __syncthreads();
    for (int i = threadIdx.y; i < 32; i += 8) {
        float x = tile[threadIdx.x][i];
        __nv_bfloat16 hi = __float2bfloat16(x);
        size_t o = (size_t)(j0 + i) * KXP + k0 + threadIdx.x;
        g_WxTh[o] = hi;
        g_WxTl[o] = __float2bfloat16(x - __bfloat162float(hi));
    }
}

// ---------------- K_convWa: Wattn [512][2048] -> WaT hi/lo [2048][512] ----------------
__global__ void k_convWa(const float* __restrict__ Wa) {
    __shared__ float tile[32][33];
    int j0 = blockIdx.x * 32, k0 = blockIdx.y * 32;
    for (int i = threadIdx.y; i < 32; i += 8)
        tile[i][threadIdx.x] = Wa[(size_t)(k0 + i) * H4 + j0 + threadIdx.x];
    __syncthreads();
    for (int i = threadIdx.y; i < 32; i += 8) {
        float x = tile[threadIdx.x][i];
        __nv_bfloat16 hi = __float2bfloat16(x);
        size_t o = (size_t)(j0 + i) * HH + k0 + threadIdx.x;
        g_WaTh[o] = hi;
        g_WaTl[o] = __float2bfloat16(x - __bfloat162float(hi));
    }
}

// ---------------- K_convWh: Wh [512][2048] -> permuted WhT hi/lo [2048][512] ----------
// out row pr(j) = ((j>>4)&31)*64 + ((j>>9)<<4) + (j&15)  (CTA-major gate grouping)
__global__ void k_convWh(const float* __restrict__ Wh) {
    __shared__ float tile[32][33];
    int j0 = blockIdx.x * 32, k0 = blockIdx.y * 32;
    for (int i = threadIdx.y; i < 32; i += 8)
        tile[i][threadIdx.x] = Wh[(size_t)(k0 + i) * H4 + j0 + threadIdx.x];
    __syncthreads();
    for (int i = threadIdx.y; i < 32; i += 8) {
        float x = tile[threadIdx.x][i];   // = Wh[k0+tx][j0+i]
        int j = j0 + i;
        int pr = ((j >> 4) & 31) * 64 + ((j >> 9) << 4) + (j & 15);
        __nv_bfloat16 hi = __float2bfloat16(x);
        size_t o = (size_t)pr * HH + k0 + threadIdx.x;
        g_WhPh[o] = hi;
        g_WhPl[o] = __float2bfloat16(x - __bfloat162float(hi));
    }
}

// ---------------- K_gatherX: x[r][c] = We[tok[r]][c] -> bf16 split, r = t*64+n --------
__global__ void k_gatherX(const int* __restrict__ caps, const float* __restrict__ We) {
    int idx = blockIdx.x * 256 + threadIdx.x;
    int r = idx / KXP, c = idx - r * KXP;
    int n = r & 63, t = r >> 6;
    float v = 0.f;
    if (c < WD) v = We[(size_t)caps[n * Tt + t] * WD + c];
    __nv_bfloat16 hi = __float2bfloat16(v);
    g_Axh[idx] = hi;
    g_Axl[idx] = __float2bfloat16(v - __bfloat162float(hi));
}

// ---------------- K_gemm3: generic bf16-split 3-product HMMA GEMM (R12-proven) -------
#define VBUF3 40960
__global__ __launch_bounds__(256)
void k_gemm3(int which, const float* __restrict__ bias, int K, int ldo) {
    const __nv_bfloat16 *Ahp, *Alp, *Bhp, *Blp;
    float* out;
    if (which == 0) { Ahp = g_Axh; Alp = g_Axl; Bhp = g_WxTh; Blp = g_WxTl; out = g_xa; }
    else            { Ahp = g_APh; Alp = g_APl; Bhp = g_WaTh; Blp = g_WaTl; out = g_AW; }

    extern __shared__ char smv[];
    uint32_t sb = smem_u32(smv);
    int tid = threadIdx.x;
    int wid = tid >> 5, lane = tid & 31;
    int warp_m = wid & 3, warp_n = wid >> 2;
    int bm = blockIdx.x, bn = blockIdx.y;

    const __nv_bfloat16* Ah0 = Ahp + (size_t)bm * 128 * K;
    const __nv_bfloat16* Al0 = Alp + (size_t)bm * 128 * K;
    const __nv_bfloat16* Bh0 = Bhp + (size_t)bn * 128 * K;
    const __nv_bfloat16* Bl0 = Blp + (size_t)bn * 128 * K;

    float acc[2][8][4];
#pragma unroll
    for (int a = 0; a < 2; a++)
#pragma unroll
        for (int t = 0; t < 8; t++)
#pragma unroll
            for (int k = 0; k < 4; k++) acc[a][t][k] = 0.f;

    int chunks = K >> 5;
    auto issue = [&](int chunk, int b) {
        int k0 = chunk * 32;
        uint32_t base = sb + b * VBUF3;
#pragma unroll
        for (int j = 0; j < 2; j++) {
            int idx = tid + j * 256;
            int r = idx >> 2, s = idx & 3;
            uint32_t doff = r * 80 + s * 16;
            size_t goff = (size_t)r * K + k0 + s * 8;
            cpasync16(base + doff,          Ah0 + goff);
            cpasync16(base + 10240 + doff,  Al0 + goff);
            cpasync16(base + 20480 + doff,  Bh0 + goff);
            cpasync16(base + 30720 + doff,  Bl0 + goff);
        }
        cp_commit();
    };

    issue(0, 0);
    for (int i = 0; i < chunks; i++) {
        int b = i & 1;
        if (i < chunks - 1) issue(i + 1, b ^ 1);
        if (i < chunks - 1) asm volatile("cp.async.wait_group 1;" ::: "memory");
        else                asm volatile("cp.async.wait_group 0;" ::: "memory");
        __syncthreads();

        uint32_t abase = sb + b * VBUF3;
#pragma unroll
        for (int kc = 0; kc < 2; kc++) {
            uint32_t ah[2][4], al[2][4], bh[4][4], bl[4][4];
#pragma unroll
            for (int tm = 0; tm < 2; tm++) {
                int row = warp_m * 32 + tm * 16 + (lane & 15);
                uint32_t ad = abase + row * 80 + kc * 32 + (lane >> 4) * 16;
                ldmx4(ah[tm], ad);
                ldmx4(al[tm], ad + 10240);
            }
#pragma unroll
            for (int g = 0; g < 4; g++) {
                int col = warp_n * 64 + g * 16 + (lane & 15);
                uint32_t bd = abase + 20480 + col * 80 + kc * 32 + (lane >> 4) * 16;
                ldmx4(bh[g], bd);
                ldmx4(bl[g], bd + 10240);
            }
#pragma unroll
            for (int tm = 0; tm < 2; tm++)
#pragma unroll
                for (int tn = 0; tn < 8; tn++) {
                    int g = tn >> 1, p = tn & 1;
                    mma16816b(acc[tm][tn], ah[tm], bh[g][p], bh[g][p + 2]);
                    mma16816b(acc[tm][tn], al[tm], bh[g][p], bh[g][p + 2]);
                    mma16816b(acc[tm][tn], ah[tm], bl[g][p], bl[g][p + 2]);
                }
        }
        __syncthreads();
    }

#pragma unroll
    for (int tm = 0; tm < 2; tm++) {
        int row = bm * 128 + warp_m * 32 + tm * 16 + (lane >> 2);
#pragma unroll
        for (int tn = 0; tn < 8; tn++) {
            int col = bn * 128 + warp_n * 64 + tn * 8 + (lane & 3) * 2;
            float b0 = bias ? bias[col] : 0.f;
            float b1 = bias ? bias[col + 1] : 0.f;
            float2 v0 = make_float2(acc[tm][tn][0] + b0, acc[tm][tn][1] + b1);
            float2 v1 = make_float2(acc[tm][tn][2] + b0, acc[tm][tn][3] + b1);
            *(float2*)&out[(size_t)row * ldo + col] = v0;
            *(float2*)&out[(size_t)(row + 8) * ldo + col] = v1;
        }
    }
}

// ---------------- K4: tensor-core LSTM step ----------------
// grid (33): block 32 = attention producer; blocks 0..31 = GEMM+gates CTAs.
// CTA c: out tile = all 64 n x (4 gates x 16 h-cols [c*16, c*16+16)), via permuted WhT.
#define SBUF 20480   // per pipeline buffer: Ah(5120) Al(5120) Bh(5120) Bl(5120)
__global__ __launch_bounds__(256)
void k_step2(int t) {
    int tid = threadIdx.x;
    int rb = t & 1, wb = rb ^ 1;

    if (blockIdx.x == 32) {
        // ---- producer: attention weights for all 64 n ----
        int p = tid & 15;
#pragma unroll
        for (int pass = 0; pass < 4; pass++) {
            int n = pass * 16 + (tid >> 4);
            const float4* hp = (const float4*)(g_h[rb] + (size_t)n * HH);
            const float4* ap = (const float4*)(g_Aproj + (size_t)(n * 16 + p) * HH);
            float s = 0.f;
#pragma unroll 8
            for (int i = 0; i < 128; i++) {
                float4 h4 = hp[i], a4 = ap[i];
                s += h4.x * a4.x + h4.y * a4.y + h4.z * a4.z + h4.w * a4.w;
            }
            s *= 0.04419417382415922f;  // 1/sqrt(512)
            float m = s;
            for (int off = 8; off; off >>= 1)
                m = fmaxf(m, __shfl_xor_sync(0xffffffffu, m, off, 16));
            float e = expf(s - m);
            float sum = e;
            for (int off = 8; off; off >>= 1)
                sum += __shfl_xor_sync(0xffffffffu, sum, off, 16);
            g_w[n * 16 + p] = e / sum;
        }
        __threadfence();
        __syncthreads();
        if (tid == 0) *((volatile unsigned int*)&g_wflag[t]) = 1u;
        return;
    }

    // ---- consumer CTA c ----
    int bc = blockIdx.x;           // h-col group [bc*16, bc*16+16)
    extern __shared__ char smv[];
    uint32_t sb = smem_u32(smv);
    int wid = tid >> 5, lane = tid & 31;
    int warp_m = wid & 3;          // 4 x 16 rows (n)
    int warp_n = wid >> 2;         // 2 x 32 cols

    const __nv_bfloat16* Bh0 = g_WhPh + (size_t)bc * 64 * HH;
    const __nv_bfloat16* Bl0 = g_WhPl + (size_t)bc * 64 * HH;

    float acc[4][4];
#pragma unroll
    for (int tn = 0; tn < 4; tn++)
#pragma unroll
        for (int k = 0; k < 4; k++) acc[tn][k] = 0.f;

    auto issue = [&](int chunk, int b) {
        int k0 = chunk * 32;
        uint32_t base = sb + b * SBUF;
        int r = tid >> 2, s = tid & 3;
        uint32_t doff = r * 80 + s * 16;
        size_t ga = (size_t)r * HH + k0 + s * 8;
        cpasync16(base + doff,          g_Hh + ga);
        cpasync16(base + 5120 + doff,   g_Hl + ga);
        cpasync16(base + 10240 + doff,  Bh0 + ga);
        cpasync16(base + 15360 + doff,  Bl0 + ga);
        cp_commit();
    };

    issue(0, 0);
#pragma unroll 1
    for (int i = 0; i < 16; i++) {
        int b = i & 1;
        if (i < 15) issue(i + 1, b ^ 1);
        if (i < 15) asm volatile("cp.async.wait_group 1;" ::: "memory");
        else        asm volatile("cp.async.wait_group 0;" ::: "memory");
        __syncthreads();

        uint32_t abase = sb + b * SBUF;
#pragma unroll
        for (int kc = 0; kc < 2; kc++) {
            uint32_t ah[4], al[4], bh[2][4], bl[2][4];
            int row = warp_m * 16 + (lane & 15);
            uint32_t ad = abase + row * 80 + kc * 32 + (lane >> 4) * 16;
            ldmx4(ah, ad);
            ldmx4(al, ad + 5120);
#pragma unroll
            for (int g = 0; g < 2; g++) {
                int col = warp_n * 32 + g * 16 + (lane & 15);
                uint32_t bd = abase + 10240 + col * 80 + kc * 32 + (lane >> 4) * 16;
                ldmx4(bh[g], bd);
                ldmx4(bl[g], bd + 5120);
            }
#pragma unroll
            for (int tn = 0; tn < 4; tn++) {
                int g = tn >> 1, p = tn & 1;
                mma16816b(acc[tn], ah, bh[g][p], bh[g][p + 2]);
                mma16816b(acc[tn], al, bh[g][p], bh[g][p + 2]);
                mma16816b(acc[tn], ah, bl[g][p], bl[g][p + 2]);
            }
        }
        __syncthreads();
    }

    // stage a_hat (64 n x 64 cols) into smem; cols cc = gate*16 + hcl
    float* a_sm = (float*)smv;                  // 64 x 68 floats = 17408 B
    float* w_sm = (float*)(smv + 17408);        // 64 x 16 floats = 4096 B
    __syncthreads();
    {
        int r0 = warp_m * 16 + (lane >> 2);
#pragma unroll
        for (int tn = 0; tn < 4; tn++) {
            int cc = warp_n * 32 + tn * 8 + (lane & 3) * 2;
            *(float2*)&a_sm[r0 * 68 + cc]       = make_float2(acc[tn][0], acc[tn][1]);
            *(float2*)&a_sm[(r0 + 8) * 68 + cc] = make_float2(acc[tn][2], acc[tn][3]);
        }
    }
    // wait for this step's attention weights
    if (tid == 0) {
        volatile unsigned int* f = &g_wflag[t];
        while (*f == 0u) {}
    }
    __syncthreads();
    __threadfence();
    for (int i = tid; i < Nn * PP; i += 256) w_sm[i] = __ldcg(&g_w[i]);
    __syncthreads();

    // combine + gates: 4 (n, hcl) pairs per thread
#pragma unroll
    for (int q = 0; q < 4; q++) {
        int pair = tid + q * 256;
        int n = pair >> 4, hcl = pair & 15;
        int jb = bc * 16 + hcl;
        float av0 = a_sm[n * 68 + 0 * 16 + hcl];
        float av1 = a_sm[n * 68 + 1 * 16 + hcl];
        float av2 = a_sm[n * 68 + 2 * 16 + hcl];
        float av3 = a_sm[n * 68 + 3 * 16 + hcl];
        const float* xr = g_xa + ((size_t)t * 64 + n) * H4 + jb;
        av0 += xr[0];  av1 += xr[512]; av2 += xr[1024]; av3 += xr[1536];
        const float* awr = g_AW + (size_t)n * 16 * H4 + jb;
#pragma unroll 4
        for (int p = 0; p < 16; p++) {
            float wv = w_sm[n * 16 + p];
            const float* a4 = awr + (size_t)p * H4;
            av0 += wv * a4[0];
            av1 += wv * a4[512];
            av2 += wv * a4[1024];
            av3 += wv * a4[1536];
        }
        float gi = 1.f / (1.f + expf(-av0));
        float gf = 1.f / (1.f + expf(-av1));
        float go = 1.f / (1.f + expf(-av2));
        float gg = tanhf(av3);
        float cp = g_c[n * HH + jb];
        float cn = gf * cp + gi * gg;
        float hn = go * tanhf(cn);
        g_c[n * HH + jb] = cn;
        g_h[wb][n * HH + jb] = hn;
        __nv_bfloat16 hi = __float2bfloat16(hn);
        g_Hh[n * HH + jb] = hi;
        g_Hl[n * HH + jb] = __float2bfloat16(hn - __bfloat162float(hi));
        g_Ah[(size_t)(n * Tt + t) * HH + jb] = __float2half(hn);
    }
}

// ---------------- K_convB: Wv [512][32000] fp32 -> g_BhT [32000][512] fp16 ----------
__global__ void k_convB(const float* __restrict__ Wv) {
    __shared__ float tile[32][33];
    int v0 = blockIdx.x * 32, k0 = blockIdx.y * 32;
    for (int i = threadIdx.y; i < 32; i += 8)
        tile[i][threadIdx.x] = Wv[(size_t)(k0 + i) * VV + v0 + threadIdx.x];
    __syncthreads();
    for (int i = threadIdx.y; i < 32; i += 8)
        g_BhT[(size_t)(v0 + i) * HH + k0 + threadIdx.x] = __float2half(tile[threadIdx.x][i]);
}

// ---------------- K5: fp16 HMMA vocab GEMM (R11-proven) ----------------
#define VBUF 20480
__global__ __launch_bounds__(256)
void k_vocab_mma(const float* __restrict__ bv, float* __restrict__ out) {
    extern __shared__ char smv[];
    uint32_t sb = smem_u32(smv);
    int tid = threadIdx.x;
    int wid = tid >> 5, lane = tid & 31;
    int warp_m = wid & 3;
    int warp_n = wid >> 2;
    int bm = blockIdx.x, bn = blockIdx.y;

    const __half* Ah0 = g_Ah + (size_t)bm * 128 * HH;
    const __half* Bh0 = g_BhT + (size_t)bn * 128 * HH;

    float acc[2][8][4];
#pragma unroll
    for (int a = 0; a < 2; a++)
#pragma unroll
        for (int t = 0; t < 8; t++)
#pragma unroll
            for (int k = 0; k < 4; k++) acc[a][t][k] = 0.f;

    auto issue = [&](int chunk, int b) {
        int k0 = chunk * 32;
        uint32_t base = sb + b * VBUF;
#pragma unroll
        for (int j = 0; j < 2; j++) {
            int idx = tid + j * 256;
            int r = idx >> 2, s = idx & 3;
            uint32_t doff = r * 80 + s * 16;
            size_t goff = (size_t)r * HH + k0 + s * 8;
            cpasync16(base + doff,          Ah0 + goff);
            cpasync16(base + 10240 + doff,  Bh0 + goff);
        }
        cp_commit();
    };

    issue(0, 0);
    for (int i = 0; i < 16; i++) {
        int b = i & 1;
        if (i < 15) issue(i + 1, b ^ 1);
        if (i < 15) asm volatile("cp.async.wait_group 1;" ::: "memory");
        else        asm volatile("cp.async.wait_group 0;" ::: "memory");
        __syncthreads();

        uint32_t abase = sb + b * VBUF;
#pragma unroll
        for (int kc = 0; kc < 2; kc++) {
            uint32_t ah[2][4], bh[4][4];
#pragma unroll
            for (int tm = 0; tm < 2; tm++) {
                int row = warp_m * 32 + tm * 16 + (lane & 15);
                ldmx4(ah[tm], abase + row * 80 + kc * 32 + (lane >> 4) * 16);
            }
#pragma unroll
            for (int g = 0; g < 4; g++) {
                int col = warp_n * 64 + g * 16 + (lane & 15);
                ldmx4(bh[g], abase + 10240 + col * 80 + kc * 32 + (lane >> 4) * 16);
            }
#pragma unroll
            for (int tm = 0; tm < 2; tm++)
#pragma unroll
                for (int tn = 0; tn < 8; tn++) {
                    int g = tn >> 1, p = tn & 1;
                    mma16816h(acc[tm][tn], ah[tm], bh[g][p], bh[g][p + 2]);
                }
        }
        __syncthreads();
    }

#pragma unroll
    for (int tm = 0; tm < 2; tm++) {
        int row = bm * 128 + warp_m * 32 + tm * 16 + (lane >> 2);
#pragma unroll
        for (int tn = 0; tn < 8; tn++) {
            int col = bn * 128 + warp_n * 64 + tn * 8 + (lane & 3) * 2;
            float b0 = bv[col], b1 = bv[col + 1];
            float2 v0 = make_float2(acc[tm][tn][0] + b0, acc[tm][tn][1] + b1);
            float2 v1 = make_float2(acc[tm][tn][2] + b0, acc[tm][tn][3] + b1);
            *(float2*)&out[(size_t)row * VV + col] = v0;
            *(float2*)&out[(size_t)(row + 8) * VV + col] = v1;
        }
    }
}

// ---------------- launcher ----------------
extern "C" void kernel_launch(void* const* d_in, const int* in_sizes, int n_in,
                              void* d_out, int out_size) {
    const float* A      = (const float*)d_in[0];
    const int*   caps   = (const int*)  d_in[1];
    const float* conv_w = (const float*)d_in[2];
    const float* conv_b = (const float*)d_in[3];
    const float* Wx     = (const float*)d_in[4];
    const float* Wh     = (const float*)d_in[5];
    const float* Wattn  = (const float*)d_in[6];
    const float* b      = (const float*)d_in[7];
    const float* We     = (const float*)d_in[8];
    const float* Wv     = (const float*)d_in[9];
    const float* bv     = (const float*)d_in[10];
    float* out = (float*)d_out;

    cudaFuncSetAttribute(k_vocab_mma, cudaFuncAttributeMaxDynamicSharedMemorySize, 2 * VBUF);
    cudaFuncSetAttribute(k_gemm3, cudaFuncAttributeMaxDynamicSharedMemorySize, 2 * VBUF3);

    k_initflags<<<1, 128>>>();
    k_convB<<<dim3(VV / 32, HH / 32), dim3(32, 8)>>>(Wv);
    k_transpose<<<dim3(DA / 32, HH / 32), dim3(32, 8)>>>(conv_w);
    k_convWx<<<dim3(H4 / 32, KXP / 32), dim3(32, 8)>>>(Wx);
    k_convWa<<<dim3(H4 / 32, HH / 32), dim3(32, 8)>>>(Wattn);
    k_convWh<<<dim3(H4 / 32, HH / 32), dim3(32, 8)>>>(Wh);
    k_gatherX<<<(Tt * Nn * KXP) / 256, 256>>>(caps, We);
    k_conv<<<256, 128>>>(A, conv_b);            // Aproj (+split) + h0/c0 (+split)
    k_gemm3<<<dim3(16, 16), 256, 2 * VBUF3>>>(0, b, KXP, H4);       // xa
    k_gemm3<<<dim3(8, 16), 256, 2 * VBUF3>>>(1, nullptr, HH, H4);   // AW
    for (int t = 0; t < Tt; t++)
        k_step2<<<33, 256, 2 * SBUF>>>(t);      // tensor-core recurrent step
    k_vocab_mma<<<dim3(16, 250), 256, 2 * VBUF>>>(bv, out);
}

// round 16
// speedup vs baseline: 2.1675x; 2.1675x over previous
#include <cuda_runtime.h>
#include <cuda_fp16.h>
#include <cuda_bf16.h>
#include <math.h>
#include <stdint.h>

#define Nn 64
#define Tt 32
#define DA 1280
#define PP 16
#define HH 512
#define H4 2048
#define WD 300
#define KXP 320     // Wx K padded 300 -> 320
#define VV 32000

// ---------------- device scratch (no allocs allowed) ----------------
__device__ float g_cwT[DA * HH];            // conv_w transposed [c][h]
__device__ float g_Aproj[Nn * PP * HH];     // [n*16+p][512] fp32 (attention dots)
__device__ float g_h[2][Nn * HH];           // double-buffered h
__device__ float g_c[Nn * HH];
__device__ float g_w[Nn * PP];              // attention weights for current step
__device__ float g_xa[Tt * Nn * H4];        // x@Wx + b, row r = t*64+n
__device__ float g_AW[Nn * PP * H4];        // Aproj@Wattn, [n*16+p][2048]
__device__ unsigned int g_wflag[Tt * 4];    // per (step, n-group) producer flags

// fp16 operands for the vocab GEMM (K-major)
__device__ __align__(16) __half g_Ah[Nn * Tt * HH];       // [2048][512], row n*32+t
__device__ __align__(16) __half g_BhT[(size_t)VV * HH];   // [32000][512]

// bf16-split operands for the xa / aw HMMA GEMMs (K-major)
__device__ __align__(16) __nv_bfloat16 g_Axh[Tt * Nn * KXP];   // gathered x, [2048][320]
__device__ __align__(16) __nv_bfloat16 g_Axl[Tt * Nn * KXP];
__device__ __align__(16) __nv_bfloat16 g_WxTh[H4 * KXP];       // Wx^T, [2048][320]
__device__ __align__(16) __nv_bfloat16 g_WxTl[H4 * KXP];
__device__ __align__(16) __nv_bfloat16 g_WaTh[H4 * HH];        // Wattn^T, [2048][512]
__device__ __align__(16) __nv_bfloat16 g_WaTl[H4 * HH];
__device__ __align__(16) __nv_bfloat16 g_APh[Nn * PP * HH];    // Aproj split, [1024][512]
__device__ __align__(16) __nv_bfloat16 g_APl[Nn * PP * HH];

// ---------------- portable PTX helpers (sm_80+ features only) ----------------
__device__ __forceinline__ uint32_t smem_u32(const void* p) {
    uint32_t a;
    asm("{ .reg .u64 t; cvta.to.shared.u64 t, %1; cvt.u32.u64 %0, t; }" : "=r"(a) : "l"(p));
    return a;
}
__device__ __forceinline__ void cpasync16(uint32_t dst, const void* src) {
    asm volatile("cp.async.cg.shared.global [%0], [%1], 16;" :: "r"(dst), "l"(src) : "memory");
}
__device__ __forceinline__ void cp_commit() {
    asm volatile("cp.async.commit_group;" ::: "memory");
}
__device__ __forceinline__ void ldmx4(uint32_t* r, uint32_t addr) {
    asm volatile("ldmatrix.sync.aligned.m8n8.x4.shared.b16 {%0,%1,%2,%3}, [%4];"
                 : "=r"(r[0]), "=r"(r[1]), "=r"(r[2]), "=r"(r[3]) : "r"(addr));
}
__device__ __forceinline__ void mma16816h(float* d, const uint32_t* a, uint32_t b0, uint32_t b1) {
    asm volatile(
        "mma.sync.aligned.m16n8k16.row.col.f32.f16.f16.f32 "
        "{%0,%1,%2,%3}, {%4,%5,%6,%7}, {%8,%9}, {%0,%1,%2,%3};"
        : "+f"(d[0]), "+f"(d[1]), "+f"(d[2]), "+f"(d[3])
        : "r"(a[0]), "r"(a[1]), "r"(a[2]), "r"(a[3]), "r"(b0), "r"(b1));
}
__device__ __forceinline__ void mma16816b(float* d, const uint32_t* a, uint32_t b0, uint32_t b1) {
    asm volatile(
        "mma.sync.aligned.m16n8k16.row.col.f32.bf16.bf16.f32 "
        "{%0,%1,%2,%3}, {%4,%5,%6,%7}, {%8,%9}, {%0,%1,%2,%3};"
        : "+f"(d[0]), "+f"(d[1]), "+f"(d[2]), "+f"(d[3])
        : "r"(a[0]), "r"(a[1]), "r"(a[2]), "r"(a[3]), "r"(b0), "r"(b1));
}

// ---------------- K0: transpose conv_w [512][1280] -> g_cwT [1280][512] ----------------
__global__ void k_transpose(const float* __restrict__ w) {
    __shared__ float tile[32][33];
    int c0 = blockIdx.x * 32, h0 = blockIdx.y * 32;
    for (int i = threadIdx.y; i < 32; i += 8)
        tile[i][threadIdx.x] = w[(h0 + i) * DA + c0 + threadIdx.x];
    __syncthreads();
    for (int i = threadIdx.y; i < 32; i += 8)
        g_cwT[(c0 + i) * HH + h0 + threadIdx.x] = tile[threadIdx.x][i];
}

// ---------------- K_convW2: fused Wx->WxT split (blocks [0,640)) + Wattn->WaT split ----
__global__ void k_convW2(const float* __restrict__ Wx, const float* __restrict__ Wa) {
    __shared__ float tile[32][33];
    int i = blockIdx.x;
    if (i < 640) {                      // convWx: grid (64, 10)
        int j0 = (i & 63) * 32, k0 = (i >> 6) * 32;
        for (int r = threadIdx.y; r < 32; r += 8) {
            int k = k0 + r;
            tile[r][threadIdx.x] = (k < WD) ? Wx[(size_t)k * H4 + j0 + threadIdx.x] : 0.f;
        }
        __syncthreads();
        for (int r = threadIdx.y; r < 32; r += 8) {
            float x = tile[threadIdx.x][r];
            __nv_bfloat16 hi = __float2bfloat16(x);
            size_t o = (size_t)(j0 + r) * KXP + k0 + threadIdx.x;
            g_WxTh[o] = hi;
            g_WxTl[o] = __float2bfloat16(x - __bfloat162float(hi));
        }
    } else {                            // convWa: grid (64, 16)
        int i2 = i - 640;
        int j0 = (i2 & 63) * 32, k0 = (i2 >> 6) * 32;
        for (int r = threadIdx.y; r < 32; r += 8)
            tile[r][threadIdx.x] = Wa[(size_t)(k0 + r) * H4 + j0 + threadIdx.x];
        __syncthreads();
        for (int r = threadIdx.y; r < 32; r += 8) {
            float x = tile[threadIdx.x][r];
            __nv_bfloat16 hi = __float2bfloat16(x);
            size_t o = (size_t)(j0 + r) * HH + k0 + threadIdx.x;
            g_WaTh[o] = hi;
            g_WaTl[o] = __float2bfloat16(x - __bfloat162float(hi));
        }
    }
}

// ---------------- K_gatherX (+flag init): x -> bf16 split, r = t*64+n ----------------
__global__ void k_gatherX(const int* __restrict__ caps, const float* __restrict__ We) {
    if (blockIdx.x == 0 && threadIdx.x < Tt * 4) g_wflag[threadIdx.x] = 0u;
    int idx = blockIdx.x * 256 + threadIdx.x;
    int r = idx / KXP, c = idx - r * KXP;
    int n = r & 63, t = r >> 6;
    float v = 0.f;
    if (c < WD) v = We[(size_t)caps[n * Tt + t] * WD + c];
    __nv_bfloat16 hi = __float2bfloat16(v);
    g_Axh[idx] = hi;
    g_Axl[idx] = __float2bfloat16(v - __bfloat162float(hi));
}

// ---------------- K1: Aproj (fp32 + bf16-split) + fused h0/c0 ----------------
__global__ void k_conv(const float* __restrict__ A, const float* __restrict__ cb) {
    int n = blockIdx.x >> 2, cg = blockIdx.x & 3;
    int j = cg * 128 + threadIdx.x;
    __shared__ float a_sm[256 * 16];
    float acc[16];
#pragma unroll
    for (int p = 0; p < 16; p++) acc[p] = 0.f;
    for (int k0 = 0; k0 < DA; k0 += 256) {
        __syncthreads();
        const float* src = A + ((size_t)n * DA + k0) * 16;
        for (int idx = threadIdx.x; idx < 256 * 16; idx += 128) a_sm[idx] = src[idx];
        __syncthreads();
#pragma unroll 4
        for (int kk = 0; kk < 256; kk++) {
            float w = g_cwT[(k0 + kk) * HH + j];
            const float4* ar = (const float4*)&a_sm[kk * 16];
            float4 a0 = ar[0], a1 = ar[1], a2 = ar[2], a3 = ar[3];
            acc[0]  += a0.x * w; acc[1]  += a0.y * w; acc[2]  += a0.z * w; acc[3]  += a0.w * w;
            acc[4]  += a1.x * w; acc[5]  += a1.y * w; acc[6]  += a1.z * w; acc[7]  += a1.w * w;
            acc[8]  += a2.x * w; acc[9]  += a2.y * w; acc[10] += a2.z * w; acc[11] += a2.w * w;
            acc[12] += a3.x * w; acc[13] += a3.y * w; acc[14] += a3.z * w; acc[15] += a3.w * w;
        }
    }
    float bb = cb[j];
    float s = 0.f;
#pragma unroll
    for (int p = 0; p < 16; p++) {
        float v = acc[p] + bb;
        size_t o = (size_t)(n * 16 + p) * HH + j;
        g_Aproj[o] = v;
        __nv_bfloat16 hi = __float2bfloat16(v);
        g_APh[o] = hi;
        g_APl[o] = __float2bfloat16(v - __bfloat162float(hi));
        s += acc[p];
    }
    s = s * (1.f / 16.f) + bb;          // mean_p(acc[p] + bb)
    g_h[0][n * HH + j] = s;
    g_c[n * HH + j] = s;
}

// ---------------- K_gemm3c: fused xa (z=0) + AW (z=1) bf16-split 3-product GEMM ------
#define VBUF3 40960
__global__ __launch_bounds__(256)
void k_gemm3c(const float* __restrict__ bias_in) {
    int which = blockIdx.z;
    if (which == 1 && blockIdx.x >= 8) return;   // AW has only 8 M-blocks
    const __nv_bfloat16 *Ahp, *Alp, *Bhp, *Blp;
    const float* bias;
    float* out;
    int K;
    if (which == 0) { Ahp = g_Axh; Alp = g_Axl; Bhp = g_WxTh; Blp = g_WxTl;
                      out = g_xa; bias = bias_in; K = KXP; }
    else            { Ahp = g_APh; Alp = g_APl; Bhp = g_WaTh; Blp = g_WaTl;
                      out = g_AW; bias = nullptr; K = HH; }

    extern __shared__ char smv[];
    uint32_t sb = smem_u32(smv);
    int tid = threadIdx.x;
    int wid = tid >> 5, lane = tid & 31;
    int warp_m = wid & 3, warp_n = wid >> 2;
    int bm = blockIdx.x, bn = blockIdx.y;

    const __nv_bfloat16* Ah0 = Ahp + (size_t)bm * 128 * K;
    const __nv_bfloat16* Al0 = Alp + (size_t)bm * 128 * K;
    const __nv_bfloat16* Bh0 = Bhp + (size_t)bn * 128 * K;
    const __nv_bfloat16* Bl0 = Blp + (size_t)bn * 128 * K;

    float acc[2][8][4];
#pragma unroll
    for (int a = 0; a < 2; a++)
#pragma unroll
        for (int t = 0; t < 8; t++)
#pragma unroll
            for (int k = 0; k < 4; k++) acc[a][t][k] = 0.f;

    int chunks = K >> 5;
    auto issue = [&](int chunk, int b) {
        int k0 = chunk * 32;
        uint32_t base = sb + b * VBUF3;
#pragma unroll
        for (int j = 0; j < 2; j++) {
            int idx = tid + j * 256;
            int r = idx >> 2, s = idx & 3;
            uint32_t doff = r * 80 + s * 16;
            size_t goff = (size_t)r * K + k0 + s * 8;
            cpasync16(base + doff,          Ah0 + goff);
            cpasync16(base + 10240 + doff,  Al0 + goff);
            cpasync16(base + 20480 + doff,  Bh0 + goff);
            cpasync16(base + 30720 + doff,  Bl0 + goff);
        }
        cp_commit();
    };

    issue(0, 0);
    for (int i = 0; i < chunks; i++) {
        int b = i & 1;
        if (i < chunks - 1) issue(i + 1, b ^ 1);
        if (i < chunks - 1) asm volatile("cp.async.wait_group 1;" ::: "memory");
        else                asm volatile("cp.async.wait_group 0;" ::: "memory");
        __syncthreads();

        uint32_t abase = sb + b * VBUF3;
#pragma unroll
        for (int kc = 0; kc < 2; kc++) {
            uint32_t ah[2][4], al[2][4], bh[4][4], bl[4][4];
#pragma unroll
            for (int tm = 0; tm < 2; tm++) {
                int row = warp_m * 32 + tm * 16 + (lane & 15);
                uint32_t ad = abase + row * 80 + kc * 32 + (lane >> 4) * 16;
                ldmx4(ah[tm], ad);
                ldmx4(al[tm], ad + 10240);
            }
#pragma unroll
            for (int g = 0; g < 4; g++) {
                int col = warp_n * 64 + g * 16 + (lane & 15);
                uint32_t bd = abase + 20480 + col * 80 + kc * 32 + (lane >> 4) * 16;
                ldmx4(bh[g], bd);
                ldmx4(bl[g], bd + 10240);
            }
#pragma unroll
            for (int tm = 0; tm < 2; tm++)
#pragma unroll
                for (int tn = 0; tn < 8; tn++) {
                    int g = tn >> 1, p = tn & 1;
                    mma16816b(acc[tm][tn], ah[tm], bh[g][p], bh[g][p + 2]);
                    mma16816b(acc[tm][tn], al[tm], bh[g][p], bh[g][p + 2]);
                    mma16816b(acc[tm][tn], ah[tm], bl[g][p], bl[g][p + 2]);
                }
        }
        __syncthreads();
    }

#pragma unroll
    for (int tm = 0; tm < 2; tm++) {
        int row = bm * 128 + warp_m * 32 + tm * 16 + (lane >> 2);
#pragma unroll
        for (int tn = 0; tn < 8; tn++) {
            int col = bn * 128 + warp_n * 64 + tn * 8 + (lane & 3) * 2;
            float b0 = bias ? bias[col] : 0.f;
            float b1 = bias ? bias[col + 1] : 0.f;
            float2 v0 = make_float2(acc[tm][tn][0] + b0, acc[tm][tn][1] + b1);
            float2 v1 = make_float2(acc[tm][tn][2] + b0, acc[tm][tn][3] + b1);
            *(float2*)&out[(size_t)row * H4 + col] = v0;
            *(float2*)&out[(size_t)(row + 8) * H4 + col] = v1;
        }
    }
}

// ---------------- K4: fused LSTM step (R12-proven: attw producers in same launch) -----
// grid (33, 4): bx<32 = consumer (hc-group), bx==32 = attention producer for n-group by.
__global__ void k_step(const float* __restrict__ Wh, int t) {
    int rb = t & 1, wb = rb ^ 1;
    int ng = blockIdx.y;
    int n0 = ng * 16;
    int tid = threadIdx.x;

    if (blockIdx.x == 32) {
        // ---- producer: attention weights for this n-group ----
        int n_l = tid >> 4, p = tid & 15;
        int n = n0 + n_l;
        const float4* hp = (const float4*)(g_h[rb] + (size_t)n * HH);
        const float4* ap = (const float4*)(g_Aproj + (size_t)(n * 16 + p) * HH);
        float s = 0.f;
#pragma unroll 8
        for (int i = 0; i < 128; i++) {
            float4 h4 = hp[i], a4 = ap[i];
            s += h4.x * a4.x + h4.y * a4.y + h4.z * a4.z + h4.w * a4.w;
        }
        s *= 0.04419417382415922f;  // 1/sqrt(512)
        float m = s;
        for (int off = 8; off; off >>= 1)
            m = fmaxf(m, __shfl_xor_sync(0xffffffffu, m, off, 16));
        float e = expf(s - m);
        float sum = e;
        for (int off = 8; off; off >>= 1)
            sum += __shfl_xor_sync(0xffffffffu, sum, off, 16);
        g_w[n * 16 + p] = e / sum;
        __threadfence();
        __syncthreads();
        if (tid == 0) *((volatile unsigned int*)&g_wflag[t * 4 + ng]) = 1u;
        return;
    }

    // ---- consumer ----
    int hc0 = blockIdx.x * 16;
    __shared__ float h_sm[16][512];
    __shared__ float red_sm[3][16][64];
    __shared__ float w_sm[16][16];
    for (int idx = tid; idx < 16 * 512; idx += 256) {
        int r = idx >> 9, k = idx & 511;
        h_sm[r][k] = g_h[rb][(n0 + r) * HH + k];
    }
    __syncthreads();

    int c = tid & 63;
    int ks = tid >> 6;
    int gate = c >> 4, hcl = c & 15;
    int j = gate * HH + hc0 + hcl;
    const float* whcol = Wh + j;

    float acc[16];
#pragma unroll
    for (int r = 0; r < 16; r++) acc[r] = 0.f;

    int kbeg = ks * 128;
    for (int k = kbeg; k < kbeg + 128; k += 4) {
        float w0 = whcol[(k + 0) * H4];
        float w1 = whcol[(k + 1) * H4];
        float w2 = whcol[(k + 2) * H4];
        float w3 = whcol[(k + 3) * H4];
#pragma unroll
        for (int r = 0; r < 16; r++) {
            float4 h4 = *(const float4*)&h_sm[r][k];
            acc[r] += h4.x * w0 + h4.y * w1 + h4.z * w2 + h4.w * w3;
        }
    }

    // wait for this step's attention weights (plain volatile poll — no atomics)
    if (tid == 0) {
        volatile unsigned int* f = &g_wflag[t * 4 + ng];
        while (*f == 0u) {}
    }
    __syncthreads();
    __threadfence();
    w_sm[tid >> 4][tid & 15] = __ldcg(&g_w[(n0 + (tid >> 4)) * 16 + (tid & 15)]);
    __syncthreads();

#pragma unroll
    for (int pp = 0; pp < 4; pp++) {
        int p = ks * 4 + pp;
#pragma unroll
        for (int r = 0; r < 16; r++)
            acc[r] += w_sm[r][p] * g_AW[((size_t)(n0 + r) * 16 + p) * H4 + j];
    }
    if (ks) {
#pragma unroll
        for (int r = 0; r < 16; r++) red_sm[ks - 1][r][c] = acc[r];
    }
    __syncthreads();
    float aval[16];
    if (ks == 0) {
#pragma unroll
        for (int r = 0; r < 16; r++) {
            float a = acc[r] + red_sm[0][r][c] + red_sm[1][r][c] + red_sm[2][r][c];
            a += g_xa[((size_t)t * 64 + n0 + r) * H4 + j];
            aval[r] = a;
        }
    }
    __syncthreads();
    if (ks == 0) {
#pragma unroll
        for (int r = 0; r < 16; r++) red_sm[0][r][c] = aval[r];
    }
    __syncthreads();
    {
        int r = tid >> 4, hl = tid & 15;
        float ai = red_sm[0][r][0 * 16 + hl];
        float af = red_sm[0][r][1 * 16 + hl];
        float ao = red_sm[0][r][2 * 16 + hl];
        float ag = red_sm[0][r][3 * 16 + hl];
        float gi = 1.f / (1.f + expf(-ai));
        float gf = 1.f / (1.f + expf(-af));
        float go = 1.f / (1.f + expf(-ao));
        float gg = tanhf(ag);
        int n = n0 + r, hg = hc0 + hl;
        float cp = g_c[n * HH + hg];
        float cn = gf * cp + gi * gg;
        float hn = go * tanhf(cn);
        g_c[n * HH + hg] = cn;
        g_h[wb][n * HH + hg] = hn;
        g_Ah[(size_t)(n * Tt + t) * HH + hg] = __float2half(hn);
    }
}

// ---------------- K_convB: Wv [512][32000] fp32 -> g_BhT [32000][512] fp16 ----------
__global__ void k_convB(const float* __restrict__ Wv) {
    __shared__ float tile[32][33];
    int v0 = blockIdx.x * 32, k0 = blockIdx.y * 32;
    for (int i = threadIdx.y; i < 32; i += 8)
        tile[i][threadIdx.x] = Wv[(size_t)(k0 + i) * VV + v0 + threadIdx.x];
    __syncthreads();
    for (int i = threadIdx.y; i < 32; i += 8)
        g_BhT[(size_t)(v0 + i) * HH + k0 + threadIdx.x] = __float2half(tile[threadIdx.x][i]);
}

// ---------------- K5: fp16 HMMA vocab GEMM (R11-proven) ----------------
#define VBUF 20480
__global__ __launch_bounds__(256)
void k_vocab_mma(const float* __restrict__ bv, float* __restrict__ out) {
    extern __shared__ char smv[];
    uint32_t sb = smem_u32(smv);
    int tid = threadIdx.x;
    int wid = tid >> 5, lane = tid & 31;
    int warp_m = wid & 3;
    int warp_n = wid >> 2;
    int bm = blockIdx.x, bn = blockIdx.y;

    const __half* Ah0 = g_Ah + (size_t)bm * 128 * HH;
    const __half* Bh0 = g_BhT + (size_t)bn * 128 * HH;

    float acc[2][8][4];
#pragma unroll
    for (int a = 0; a < 2; a++)
#pragma unroll
        for (int t = 0; t < 8; t++)
#pragma unroll
            for (int k = 0; k < 4; k++) acc[a][t][k] = 0.f;

    auto issue = [&](int chunk, int b) {
        int k0 = chunk * 32;
        uint32_t base = sb + b * VBUF;
#pragma unroll
        for (int j = 0; j < 2; j++) {
            int idx = tid + j * 256;
            int r = idx >> 2, s = idx & 3;
            uint32_t doff = r * 80 + s * 16;
            size_t goff = (size_t)r * HH + k0 + s * 8;
            cpasync16(base + doff,          Ah0 + goff);
            cpasync16(base + 10240 + doff,  Bh0 + goff);
        }
        cp_commit();
    };

    issue(0, 0);
    for (int i = 0; i < 16; i++) {
        int b = i & 1;
        if (i < 15) issue(i + 1, b ^ 1);
        if (i < 15) asm volatile("cp.async.wait_group 1;" ::: "memory");
        else        asm volatile("cp.async.wait_group 0;" ::: "memory");
        __syncthreads();

        uint32_t abase = sb + b * VBUF;
#pragma unroll
        for (int kc = 0; kc < 2; kc++) {
            uint32_t ah[2][4], bh[4][4];
#pragma unroll
            for (int tm = 0; tm < 2; tm++) {
                int row = warp_m * 32 + tm * 16 + (lane & 15);
                ldmx4(ah[tm], abase + row * 80 + kc * 32 + (lane >> 4) * 16);
            }
#pragma unroll
            for (int g = 0; g < 4; g++) {
                int col = warp_n * 64 + g * 16 + (lane & 15);
                ldmx4(bh[g], abase + 10240 + col * 80 + kc * 32 + (lane >> 4) * 16);
            }
#pragma unroll
            for (int tm = 0; tm < 2; tm++)
#pragma unroll
                for (int tn = 0; tn < 8; tn++) {
                    int g = tn >> 1, p = tn & 1;
                    mma16816h(acc[tm][tn], ah[tm], bh[g][p], bh[g][p + 2]);
                }
        }
        __syncthreads();
    }

#pragma unroll
    for (int tm = 0; tm < 2; tm++) {
        int row = bm * 128 + warp_m * 32 + tm * 16 + (lane >> 2);
#pragma unroll
        for (int tn = 0; tn < 8; tn++) {
            int col = bn * 128 + warp_n * 64 + tn * 8 + (lane & 3) * 2;
            float b0 = bv[col], b1 = bv[col + 1];
            float2 v0 = make_float2(acc[tm][tn][0] + b0, acc[tm][tn][1] + b1);
            float2 v1 = make_float2(acc[tm][tn][2] + b0, acc[tm][tn][3] + b1);
            *(float2*)&out[(size_t)row * VV + col] = v0;
            *(float2*)&out[(size_t)(row + 8) * VV + col] = v1;
        }
    }
}

// ---------------- launcher ----------------
// Launch order arranged so the 6th launch (ncu -s 5 -c 1) is k_step(t=0).
extern "C" void kernel_launch(void* const* d_in, const int* in_sizes, int n_in,
                              void* d_out, int out_size) {
    const float* A      = (const float*)d_in[0];
    const int*   caps   = (const int*)  d_in[1];
    const float* conv_w = (const float*)d_in[2];
    const float* conv_b = (const float*)d_in[3];
    const float* Wx     = (const float*)d_in[4];
    const float* Wh     = (const float*)d_in[5];
    const float* Wattn  = (const float*)d_in[6];
    const float* b      = (const float*)d_in[7];
    const float* We     = (const float*)d_in[8];
    const float* Wv     = (const float*)d_in[9];
    const float* bv     = (const float*)d_in[10];
    float* out = (float*)d_out;

    cudaFuncSetAttribute(k_vocab_mma, cudaFuncAttributeMaxDynamicSharedMemorySize, 2 * VBUF);
    cudaFuncSetAttribute(k_gemm3c, cudaFuncAttributeMaxDynamicSharedMemorySize, 2 * VBUF3);

    k_transpose<<<dim3(DA / 32, HH / 32), dim3(32, 8)>>>(conv_w);          // 1
    k_convW2<<<1664, dim3(32, 8)>>>(Wx, Wattn);                            // 2
    k_gatherX<<<(Tt * Nn * KXP) / 256, 256>>>(caps, We);                   // 3 (+flags)
    k_conv<<<256, 128>>>(A, conv_b);                                       // 4
    k_gemm3c<<<dim3(16, 16, 2), 256, 2 * VBUF3>>>(b);                      // 5 (xa + AW)
    for (int t = 0; t < Tt; t++)
        k_step<<<dim3(33, 4), 256>>>(Wh, t);                               // 6.. (t=0 profiled)
    k_convB<<<dim3(VV / 32, HH / 32), dim3(32, 8)>>>(Wv);
    k_vocab_mma<<<dim3(16, 250), 256, 2 * VBUF>>>(bv, out);
}